// round 6
// baseline (speedup 1.0000x reference)
#include <cuda_runtime.h>
#include <math.h>

// Log-polar patch extraction — ONE BATCH PER WARP, no block barrier.
//   img:      [B,1,256,256] f32   (d_in[0])
//   kpLoc:    [B,2]         f32   (d_in[1])
//   scaling:  [B]           f32   (d_in[2])
//   rotation: [B]           f32   (d_in[3])
//   out:      [B,1,64,64]   f32
//
// Geometry: kpLoc in [-0.6,0.6], scaling in [0.5,2.0] => pixel-space sample
// radius r128 <= 2.05; all bilinear footprints fall inside the 8x8 window
// [floor(c)-3, floor(c)+4]^2, strictly interior to the 256x256 image.
//
// Per warp: lane L owns radii j = 2L, 2L+1 (radius values in registers),
// the 8x8 image window + 64-entry (cos,sin) table live in per-warp smem.
// Loop over output rows io (roll folded: i = (io-n) & 63), lane stores
// float2 -> warp writes one coalesced 256B row per iteration.

#define RES 64
#define IMG_W 256
#define PI_F 3.14159265358979323846f
#define WARPS 4

__device__ __forceinline__ float2 fma2(float2 a, float2 b, float2 c) {
    float2 d;
    asm("fma.rn.f32x2 %0, %1, %2, %3;"
        : "=l"(reinterpret_cast<unsigned long long&>(d))
        : "l"(reinterpret_cast<unsigned long long&>(a)),
          "l"(reinterpret_cast<unsigned long long&>(b)),
          "l"(reinterpret_cast<unsigned long long&>(c)));
    return d;
}

__global__ void __launch_bounds__(32 * WARPS)
logpolar_kernel(const float* __restrict__ img,
                const float* __restrict__ kpLoc,
                const float* __restrict__ scaling,
                const float* __restrict__ rotation,
                float* __restrict__ out)
{
    const int wid  = threadIdx.x >> 5;
    const int lane = threadIdx.x & 31;
    const int b    = blockIdx.x * WARPS + wid;

    __shared__ float  s_tile[WARPS][64];   // 8x8 window, pre-scaled by 1/255
    __shared__ float2 s_cs[WARPS][64];     // (cos, sin) per angle i

    // Per-batch scalars (same address across warp -> broadcast LDG)
    const float rot = rotation[b];
    const float scl = scaling[b];
    const float kx  = kpLoc[2 * b + 0];
    const float ky  = kpLoc[2 * b + 1];
    const float maxR = 6.0f * scl;

    // Sample-grid center in pixel coords; 8x8 window origin
    const float cx = kx * 128.0f + 127.5f;
    const float cy = ky * 128.0f + 127.5f;
    const float fx0 = floorf(cx);
    const float fy0 = floorf(cy);
    const int   x0  = (int)fx0 - 3;
    const int   y0  = (int)fy0 - 3;
    const float cxr = (cx - fx0) + 3.0f;   // window-relative center, in [3,4)
    const float cyr = (cy - fy0) + 3.0f;

    // ---- issue tile loads FIRST (DRAM latency overlapped by MUFU below) ----
    const float* __restrict__ im = img + (size_t)b * (IMG_W * IMG_W);
    const int t0 = lane, t1 = lane + 32;
    float p0 = __ldg(im + (y0 + (t0 >> 3)) * IMG_W + x0 + (t0 & 7));
    float p1 = __ldg(im + (y0 + (t1 >> 3)) * IMG_W + x0 + (t1 & 7));

    // ---- cos/sin table: 2 angles per lane ----
    float s0, c0, s1, c1;
    sincosf(((float)lane + 0.5f)  * (2.0f * PI_F / RES), &s0, &c0);
    sincosf(((float)lane + 32.5f) * (2.0f * PI_F / RES), &s1, &c1);

    // ---- radii for this lane's two columns j = 2*lane, 2*lane+1 (registers) ----
    const float lm = logf(maxR);
    float ra_ = expf(((2.0f * lane + 0.5f) * (1.0f / RES)) * lm);   // maxR^normGrid
    float rb_ = expf(((2.0f * lane + 1.5f) * (1.0f / RES)) * lm);
    const float sR = (maxR * (2.0f / 1500.0f)) / (maxR - 1.0f) * 128.0f;
    const float ra = (ra_ - 1.0f) * sR;     // pixel-space radius, <= 2.05
    const float rb = (rb_ - 1.0f) * sR;

    // ---- publish per-warp tables ----
    s_cs[wid][lane]        = make_float2(c0, s0);
    s_cs[wid][lane + 32]   = make_float2(c1, s1);
    s_tile[wid][t0] = p0 * (1.0f / 255.0f);
    s_tile[wid][t1] = p1 * (1.0f / 255.0f);
    __syncwarp();

    // roll amount (banker's rounding to match jnp.round)
    int n = (int)rintf(rot * 57.29577951308232f * (1.0f / 5.625f));
    n = ((n % RES) + RES) % RES;

    const float* __restrict__ tw = s_tile[wid];
    const float2* __restrict__ cw = s_cs[wid];
    const float2 cc = make_float2(cxr, cyr);
    const float2 r2a = make_float2(ra, ra);
    const float2 r2b = make_float2(rb, rb);
    float2* __restrict__ ob = reinterpret_cast<float2*>(out + (size_t)b * (RES * RES)) + lane;

    #pragma unroll 4
    for (int io = 0; io < RES; io++) {
        int i = (io - n) & 63;              // source angle (roll folded in)
        float2 cs = cw[i];                  // uniform broadcast LDS.64

        float va, vb;
        #define PIXEL(RR, OUTF)                                         \
        {                                                               \
            float2 p = fma2(RR, cs, cc);        /* (ix, iy) */          \
            float fx = floorf(p.x), fy = floorf(p.y);                   \
            float wx = p.x - fx,    wy = p.y - fy;                      \
            int   xi = (int)fx,     yi = (int)fy;                       \
            const float* q = tw + (yi << 3) + xi;                       \
            float v00 = q[0], v01 = q[1], v10 = q[8], v11 = q[9];       \
            float top = fmaf(wx, v01 - v00, v00);                       \
            float bot = fmaf(wx, v11 - v10, v10);                       \
            OUTF = fmaf(wy, bot - top, top);                            \
        }
        PIXEL(r2a, va)
        PIXEL(r2b, vb)
        #undef PIXEL

        ob[io * 32] = make_float2(va, vb);  // coalesced 256B row per warp
    }
}

extern "C" void kernel_launch(void* const* d_in, const int* in_sizes, int n_in,
                              void* d_out, int out_size)
{
    const float* img      = (const float*)d_in[0];
    const float* kpLoc    = (const float*)d_in[1];
    const float* scaling  = (const float*)d_in[2];
    const float* rotation = (const float*)d_in[3];
    float* out = (float*)d_out;

    int B = out_size / (RES * RES);       // 2048
    logpolar_kernel<<<B / WARPS, 32 * WARPS>>>(img, kpLoc, scaling, rotation, out);
}

// round 7
// speedup vs baseline: 1.1555x; 1.1555x over previous
#include <cuda_runtime.h>
#include <math.h>

// Log-polar patch extraction — 4 warps per batch, warp-autonomous (no block barrier).
//   img:      [B,1,256,256] f32   (d_in[0])
//   kpLoc:    [B,2]         f32   (d_in[1])
//   scaling:  [B]           f32   (d_in[2])
//   rotation: [B]           f32   (d_in[3])
//   out:      [B,1,64,64]   f32
//
// Geometry: kpLoc in [-0.6,0.6], scaling in [0.5,2.0] => pixel-space sample
// radius r128 <= 2.05; all bilinear footprints fall inside the 8x8 window
// [floor(c)-3, floor(c)+4]^2, strictly interior to the 256x256 image.
//
// Each warp owns 16 output rows of one batch. Lane L owns radii j = 2L, 2L+1
// (registers). Lane k holds (cos,sin) of the SOURCE angle of output row k
// (circular roll folded in before trig); the body broadcasts it with shfl.
// Only the 8x8 image window lives in (per-warp) smem.

#define RES 64
#define IMG_W 256
#define PI_F 3.14159265358979323846f
#define WPB 8           // warps per block
#define WPBATCH 4       // warps per batch (16 rows each)

__device__ __forceinline__ float2 fma2(float2 a, float2 b, float2 c) {
    float2 d;
    asm("fma.rn.f32x2 %0, %1, %2, %3;"
        : "=l"(reinterpret_cast<unsigned long long&>(d))
        : "l"(reinterpret_cast<unsigned long long&>(a)),
          "l"(reinterpret_cast<unsigned long long&>(b)),
          "l"(reinterpret_cast<unsigned long long&>(c)));
    return d;
}

__global__ void __launch_bounds__(32 * WPB)
logpolar_kernel(const float* __restrict__ img,
                const float* __restrict__ kpLoc,
                const float* __restrict__ scaling,
                const float* __restrict__ rotation,
                float* __restrict__ out)
{
    const int wid  = threadIdx.x >> 5;
    const int lane = threadIdx.x & 31;
    const int b    = blockIdx.x * (WPB / WPBATCH) + (wid >> 2);  // 2 batches / block
    const int wsub = wid & 3;                                    // row group 0..3
    const int row0 = wsub << 4;                                  // first output row

    __shared__ float s_tile[WPB][64];   // per-warp 8x8 window, pre-scaled by 1/255

    // Per-batch scalars (same address across warp -> broadcast LDG)
    const float rot = rotation[b];
    const float scl = scaling[b];
    const float kx  = kpLoc[2 * b + 0];
    const float ky  = kpLoc[2 * b + 1];
    const float maxR = 6.0f * scl;

    // Sample-grid center in pixel coords; 8x8 window origin
    const float cx = kx * 128.0f + 127.5f;
    const float cy = ky * 128.0f + 127.5f;
    const float fx0 = floorf(cx);
    const float fy0 = floorf(cy);
    const int   x0  = (int)fx0 - 3;
    const int   y0  = (int)fy0 - 3;
    const float cxr = (cx - fx0) + 3.0f;   // window-relative center, in [3,4)
    const float cyr = (cy - fy0) + 3.0f;

    // ---- tile loads first (DRAM latency overlaps the MUFU work below) ----
    const float* __restrict__ im = img + (size_t)b * (IMG_W * IMG_W);
    const int t0 = lane, t1 = lane + 32;
    float p0 = __ldg(im + (y0 + (t0 >> 3)) * IMG_W + x0 + (t0 & 7));
    float p1 = __ldg(im + (y0 + (t1 >> 3)) * IMG_W + x0 + (t1 & 7));

    // ---- roll amount (banker's rounding to match jnp.round) ----
    int n = (int)rintf(rot * 57.29577951308232f * (1.0f / 5.625f));
    n = ((n % RES) + RES) % RES;

    // ---- lane k holds (cos,sin) of source angle for output row row0+k ----
    int isrc = (row0 + (lane & 15) - n) & 63;
    float sv, cv;
    sincosf(((float)isrc + 0.5f) * (2.0f * PI_F / RES), &sv, &cv);

    // ---- radii for this lane's two columns j = 2L, 2L+1 (registers) ----
    const float lm = logf(maxR);
    float ra_ = expf(((2.0f * lane + 0.5f) * (1.0f / RES)) * lm);   // maxR^normGrid
    float rb_ = expf(((2.0f * lane + 1.5f) * (1.0f / RES)) * lm);
    const float sR = (maxR * (2.0f / 1500.0f)) / (maxR - 1.0f) * 128.0f;
    const float2 r2a = make_float2((ra_ - 1.0f) * sR, (ra_ - 1.0f) * sR);
    const float2 r2b = make_float2((rb_ - 1.0f) * sR, (rb_ - 1.0f) * sR);

    // ---- publish per-warp tile ----
    s_tile[wid][t0] = p0 * (1.0f / 255.0f);
    s_tile[wid][t1] = p1 * (1.0f / 255.0f);
    __syncwarp();

    const float* __restrict__ tw = s_tile[wid];
    const float2 cc = make_float2(cxr, cyr);
    float2* __restrict__ ob =
        reinterpret_cast<float2*>(out + (size_t)b * (RES * RES) + row0 * RES) + lane;

    #pragma unroll 4
    for (int k = 0; k < 16; k++) {
        float2 cs;
        cs.x = __shfl_sync(0xffffffffu, cv, k);   // uniform broadcast
        cs.y = __shfl_sync(0xffffffffu, sv, k);

        float va, vb;
        #define PIXEL(RR, OUTF)                                         \
        {                                                               \
            float2 p = fma2(RR, cs, cc);        /* (ix, iy) */          \
            float fx = floorf(p.x), fy = floorf(p.y);                   \
            float wx = p.x - fx,    wy = p.y - fy;                      \
            int   xi = (int)fx,     yi = (int)fy;                       \
            const float* q = tw + (yi << 3) + xi;                       \
            float v00 = q[0], v01 = q[1], v10 = q[8], v11 = q[9];       \
            float top = fmaf(wx, v01 - v00, v00);                       \
            float bot = fmaf(wx, v11 - v10, v10);                       \
            OUTF = fmaf(wy, bot - top, top);                            \
        }
        PIXEL(r2a, va)
        PIXEL(r2b, vb)
        #undef PIXEL

        ob[k * 32] = make_float2(va, vb);   // coalesced 256B row per warp
    }
}

extern "C" void kernel_launch(void* const* d_in, const int* in_sizes, int n_in,
                              void* d_out, int out_size)
{
    const float* img      = (const float*)d_in[0];
    const float* kpLoc    = (const float*)d_in[1];
    const float* scaling  = (const float*)d_in[2];
    const float* rotation = (const float*)d_in[3];
    float* out = (float*)d_out;

    int B = out_size / (RES * RES);                    // 2048
    int blocks = B * WPBATCH / WPB;                    // 1024
    logpolar_kernel<<<blocks, 32 * WPB>>>(img, kpLoc, scaling, rotation, out);
}